// round 17
// baseline (speedup 1.0000x reference)
#include <cuda_runtime.h>
#include <cuda_fp16.h>
#include <mma.h>

#define NN 100000
#define NPAD (NN + 64)
#define NE 1600000
#define SCAN_B 1024
#define SCAN_NB ((NN + SCAN_B - 1) / SCAN_B)   // 98

// Scratch (static device globals — zero-initialized; padded +64 rows for wmma)
__device__ uint2  g_zsh[NN * 16];     // z * dinv   [N,64] fp16
__device__ uint2  g_x1h[NPAD * 32];   // relu(gcn1) [N,128] fp16
__device__ uint2  g_hs2h[NPAD * 16];  // (x1@W2)*dinv [N,64] fp16
__device__ float  g_dinv[NPAD];
__device__ int    g_cnt[NN];        // in-degree (edges only)
__device__ int    g_off[NN];        // CSR row offsets (exclusive prefix of cnt)
__device__ int    g_cur[NN];        // mutable cursor for permute
__device__ int    g_esrc[NE];       // src indices sorted by dst
__device__ int    g_bsum[128];      // scan block sums (raw totals from scan1)
__device__ int    g_layout;         // 1 = int64 pairs, 0 = int32

__device__ __forceinline__ uint2 pack_h4(float4 v) {
    __half2 a = __floats2half2_rn(v.x, v.y);
    __half2 b = __floats2half2_rn(v.z, v.w);
    uint2 u;
    u.x = *(unsigned*)&a;
    u.y = *(unsigned*)&b;
    return u;
}
__device__ __forceinline__ void acc_h4(float4& acc, uint2 u) {
    float2 f0 = __half22float2(*(__half2*)&u.x);
    float2 f1 = __half22float2(*(__half2*)&u.y);
    acc.x += f0.x; acc.y += f0.y; acc.z += f1.x; acc.w += f1.y;
}

// Shared gather core: fp16 payload segment sum for (node, f), fp32 accumulate.
__device__ __forceinline__ float4 gather_node(const uint2* __restrict__ hs,
                                              int node, int f) {
    float4 acc = make_float4(0.f, 0.f, 0.f, 0.f);
    acc_h4(acc, __ldg(hs + (size_t)node * 16 + f));  // self-loop seed
    int j = g_off[node];
    int end = j + g_cnt[node];
    for (; j + 8 <= end; j += 8) {
        int s0 = __ldg(&g_esrc[j]);
        int s1 = __ldg(&g_esrc[j + 1]);
        int s2 = __ldg(&g_esrc[j + 2]);
        int s3 = __ldg(&g_esrc[j + 3]);
        int s4 = __ldg(&g_esrc[j + 4]);
        int s5 = __ldg(&g_esrc[j + 5]);
        int s6 = __ldg(&g_esrc[j + 6]);
        int s7 = __ldg(&g_esrc[j + 7]);
        uint2 u0 = __ldg(hs + (size_t)s0 * 16 + f);
        uint2 u1 = __ldg(hs + (size_t)s1 * 16 + f);
        uint2 u2 = __ldg(hs + (size_t)s2 * 16 + f);
        uint2 u3 = __ldg(hs + (size_t)s3 * 16 + f);
        uint2 u4 = __ldg(hs + (size_t)s4 * 16 + f);
        uint2 u5 = __ldg(hs + (size_t)s5 * 16 + f);
        uint2 u6 = __ldg(hs + (size_t)s6 * 16 + f);
        uint2 u7 = __ldg(hs + (size_t)s7 * 16 + f);
        acc_h4(acc, u0); acc_h4(acc, u1); acc_h4(acc, u2); acc_h4(acc, u3);
        acc_h4(acc, u4); acc_h4(acc, u5); acc_h4(acc, u6); acc_h4(acc, u7);
    }
    if (j + 4 <= end) {
        int s0 = __ldg(&g_esrc[j]);
        int s1 = __ldg(&g_esrc[j + 1]);
        int s2 = __ldg(&g_esrc[j + 2]);
        int s3 = __ldg(&g_esrc[j + 3]);
        uint2 u0 = __ldg(hs + (size_t)s0 * 16 + f);
        uint2 u1 = __ldg(hs + (size_t)s1 * 16 + f);
        uint2 u2 = __ldg(hs + (size_t)s2 * 16 + f);
        uint2 u3 = __ldg(hs + (size_t)s3 * 16 + f);
        acc_h4(acc, u0); acc_h4(acc, u1); acc_h4(acc, u2); acc_h4(acc, u3);
        j += 4;
    }
    for (; j < end; ++j) {
        int s0 = __ldg(&g_esrc[j]);
        acc_h4(acc, __ldg(hs + (size_t)s0 * 16 + f));
    }
    return acc;
}

// Detection only (g_cnt zeroing via cudaMemsetAsync).
__global__ void k_detect(const int* __restrict__ ei) {
    __shared__ int nz;
    if (threadIdx.x == 0) nz = 0;
    __syncthreads();
    if (ei[2 * threadIdx.x + 1] != 0) atomicOr(&nz, 1);
    __syncthreads();
    if (threadIdx.x == 0) g_layout = (nz == 0) ? 1 : 0;
}

__device__ __forceinline__ int edge_src(const int* __restrict__ ei, int e, int layout) {
    return layout ? ei[2 * e] : ei[e];
}
__device__ __forceinline__ int edge_dst(const int* __restrict__ ei, int e, int layout) {
    return layout ? ei[2 * (NE + e)] : ei[NE + e];
}

// Histogram of destinations, 4 edges/thread via int4 (int32 path)
__global__ void k_hist(const int* __restrict__ ei) {
    int t = blockIdx.x * 256 + threadIdx.x;
    int e = t * 4;
    if (e >= NE) return;
    if (g_layout == 0) {
        int4 d4 = __ldg((const int4*)(ei + NE) + t);
        if ((unsigned)d4.x < NN) atomicAdd(&g_cnt[d4.x], 1);
        if ((unsigned)d4.y < NN) atomicAdd(&g_cnt[d4.y], 1);
        if ((unsigned)d4.z < NN) atomicAdd(&g_cnt[d4.z], 1);
        if ((unsigned)d4.w < NN) atomicAdd(&g_cnt[d4.w], 1);
    } else {
#pragma unroll
        for (int q = 0; q < 4; ++q) {
            int d = edge_dst(ei, e + q, 1);
            if ((unsigned)d < NN) atomicAdd(&g_cnt[d], 1);
        }
    }
}

// Block-level exclusive scan (Hillis-Steele), emits per-block totals.
__global__ void k_scan1() {
    __shared__ int sh[SCAN_B];
    int i = blockIdx.x * SCAN_B + threadIdx.x;
    int v = (i < NN) ? g_cnt[i] : 0;
    sh[threadIdx.x] = v;
    __syncthreads();
#pragma unroll
    for (int ofs = 1; ofs < SCAN_B; ofs <<= 1) {
        int t = (threadIdx.x >= ofs) ? sh[threadIdx.x - ofs] : 0;
        __syncthreads();
        sh[threadIdx.x] += t;
        __syncthreads();
    }
    if (i < NN) g_off[i] = sh[threadIdx.x] - v;   // exclusive
    if (threadIdx.x == SCAN_B - 1) g_bsum[blockIdx.x] = sh[SCAN_B - 1];
}

// Fused scan2 + scan3 + scale_init. 2 units (uint2 columns) per thread.
__global__ void k_prep(const float4* __restrict__ z4) {
    __shared__ int bs[128];
    int t = threadIdx.x;
    if (t < 128) bs[t] = (t < SCAN_NB) ? g_bsum[t] : 0;
    __syncthreads();
    int v0 = (t < 128) ? bs[t] : 0;
#pragma unroll
    for (int ofs = 1; ofs < 128; ofs <<= 1) {
        int tv = (t < 128 && t >= ofs) ? bs[t - ofs] : 0;
        __syncthreads();
        if (t < 128) bs[t] += tv;
        __syncthreads();
    }
    if (t < 128) bs[t] -= v0;   // exclusive
    __syncthreads();

    int u0 = (blockIdx.x * 256 + t) * 2;   // exactly NN*16 units total
#pragma unroll
    for (int q = 0; q < 2; ++q) {
        int u = u0 + q;
        int node = u >> 4;
        int f = u & 15;
        float dinv = rsqrtf((float)g_cnt[node] + 1.0f);
        if (f == 0) {
            int o = g_off[node] + bs[node >> 10];
            g_off[node] = o;
            g_cur[node] = o;
            g_dinv[node] = dinv;
        }
        float4 v = __ldg(z4 + u);
        v.x *= dinv; v.y *= dinv; v.z *= dinv; v.w *= dinv;
        g_zsh[u] = pack_h4(v);
    }
}

// Counting-sort edges by destination, 4 edges/thread via int4 (int32 path)
__global__ void k_permute(const int* __restrict__ ei) {
    int t = blockIdx.x * 256 + threadIdx.x;
    int e = t * 4;
    if (e >= NE) return;
    if (g_layout == 0) {
        int4 s4 = __ldg((const int4*)ei + t);
        int4 d4 = __ldg((const int4*)(ei + NE) + t);
        if ((unsigned)s4.x < NN && (unsigned)d4.x < NN) g_esrc[atomicAdd(&g_cur[d4.x], 1)] = s4.x;
        if ((unsigned)s4.y < NN && (unsigned)d4.y < NN) g_esrc[atomicAdd(&g_cur[d4.y], 1)] = s4.y;
        if ((unsigned)s4.z < NN && (unsigned)d4.z < NN) g_esrc[atomicAdd(&g_cur[d4.z], 1)] = s4.z;
        if ((unsigned)s4.w < NN && (unsigned)d4.w < NN) g_esrc[atomicAdd(&g_cur[d4.w], 1)] = s4.w;
    } else {
#pragma unroll
        for (int q = 0; q < 4; ++q) {
            int s = edge_src(ei, e + q, 1);
            int d = edge_dst(ei, e + q, 1);
            if ((unsigned)s < NN && (unsigned)d < NN)
                g_esrc[atomicAdd(&g_cur[d], 1)] = s;
        }
    }
}

// Standalone gather (layer 2): 16 threads per node, one 4-feature column each.
// out = d_out = sum * dinv[dst] + b2 (fp32)
__global__ void k_gather2(float4* __restrict__ dout, const float4* __restrict__ b2v) {
    int gt = blockIdx.x * 256 + threadIdx.x;  // exactly NN*16 threads
    int node = gt >> 4;
    int f = gt & 15;
    float4 acc = gather_node((const uint2*)g_hs2h, node, f);
    float sc = g_dinv[node];
    float4 b = __ldg(b2v + f);
    acc.x = acc.x * sc + b.x; acc.y = acc.y * sc + b.y;
    acc.z = acc.z * sc + b.z; acc.w = acc.w * sc + b.w;
    dout[(size_t)node * 16 + f] = acc;
}

// FUSED gather1 + gemm1: 64 nodes/block, 256 threads (8 warps).
// Phase A: gather layer-1 aggregation (incl dinv[dst] scale) directly into
//          the wmma A-tile smem (fp16). Phase B: HMMA vs W1 (fp32->fp16),
//          relu(acc+b1) -> g_x1h. K=64, N=128.
__global__ void __launch_bounds__(256) k_fused1(const float* __restrict__ W1,
                                                const float* __restrict__ b1) {
    using namespace nvcuda;
    constexpr int K = 64, N = 128;
    constexpr int AW = K + 8;          // 72 halves
    constexpr int BW = N + 8;          // 136 halves
    constexpr int CW = N + 8;          // 136 floats
    constexpr int CT = N / 32;         // 4 col tiles per warp half
    constexpr size_t SZ_AB = (size_t)64 * AW * 2 + (size_t)K * BW * 2;
    constexpr size_t SZ_C  = (size_t)64 * CW * 4;
    constexpr size_t SZ = SZ_AB > SZ_C ? SZ_AB : SZ_C;

    __shared__ __align__(16) char smraw[SZ];
    __half* As = (__half*)smraw;
    __half* Bs = As + 64 * AW;
    float*  Cs = (float*)smraw;

    int tid = threadIdx.x;
    int row0 = blockIdx.x * 64;

    // Stage B: convert W1 fp32 -> fp16 (2048 float4 / 256 thr = 8 each)
#pragma unroll
    for (int j = tid; j < K * (N / 4); j += 256) {
        float4 w = __ldg((const float4*)W1 + j);
        int r = j / (N / 4), c4 = j % (N / 4);
        *(uint2*)&Bs[r * BW + c4 * 4] = pack_h4(w);
    }

    // Phase A: gather 64 rows, 16 threads/node, 4 passes
    int f = tid & 15;
    int ng = tid >> 4;                 // 0..15
#pragma unroll
    for (int pass = 0; pass < 4; ++pass) {
        int r = pass * 16 + ng;
        int node = row0 + r;
        float4 acc = make_float4(0.f, 0.f, 0.f, 0.f);
        if (node < NN) {
            acc = gather_node((const uint2*)g_zsh, node, f);
            float sc = g_dinv[node];
            acc.x *= sc; acc.y *= sc; acc.z *= sc; acc.w *= sc;
        }
        *(uint2*)&As[r * AW + f * 4] = pack_h4(acc);
    }
    __syncthreads();

    // Phase B: HMMA
    int w = tid >> 5;
    int rt = w & 3;                    // row tile (16 rows)
    int ch = w >> 2;                   // column half
    int col_base = ch * (N / 2);

    wmma::fragment<wmma::accumulator, 16, 16, 16, float> acc[CT];
#pragma unroll
    for (int t = 0; t < CT; ++t) wmma::fill_fragment(acc[t], 0.0f);
#pragma unroll
    for (int k0 = 0; k0 < K / 16; ++k0) {
        wmma::fragment<wmma::matrix_a, 16, 16, 16, __half, wmma::row_major> fa;
        wmma::load_matrix_sync(fa, As + rt * 16 * AW + k0 * 16, AW);
#pragma unroll
        for (int t = 0; t < CT; ++t) {
            wmma::fragment<wmma::matrix_b, 16, 16, 16, __half, wmma::row_major> fb;
            wmma::load_matrix_sync(fb, Bs + (k0 * 16) * BW + col_base + t * 16, BW);
            wmma::mma_sync(acc[t], fa, fb, acc[t]);
        }
    }
    __syncthreads();
#pragma unroll
    for (int t = 0; t < CT; ++t)
        wmma::store_matrix_sync(Cs + rt * 16 * CW + col_base + t * 16, acc[t], CW,
                                wmma::mem_row_major);
    __syncthreads();

#pragma unroll
    for (int j = tid; j < 64 * (N / 4); j += 256) {
        int r = j / (N / 4), c4 = j % (N / 4);
        float4 v = *(float4*)&Cs[r * CW + c4 * 4];
        float4 b = __ldg((const float4*)b1 + c4);
        v.x = fmaxf(v.x + b.x, 0.f); v.y = fmaxf(v.y + b.y, 0.f);
        v.z = fmaxf(v.z + b.z, 0.f); v.w = fmaxf(v.w + b.w, 0.f);
        g_x1h[(size_t)(row0 + r) * 32 + c4] = pack_h4(v);
    }
}

// Tensor-core GEMM 2 (standalone): in=g_x1h [*,128], out=(acc*dinv) fp16 -> g_hs2h
__global__ void __launch_bounds__(256) k_gemm_wmma2(const float* __restrict__ W) {
    using namespace nvcuda;
    constexpr int K = 128, N = 64;
    constexpr int AW = K + 8;
    constexpr int BW = N + 8;
    constexpr int CW = N + 8;
    constexpr int CT = N / 32;         // 2
    constexpr size_t SZ_AB = (size_t)64 * AW * 2 + (size_t)K * BW * 2;
    constexpr size_t SZ_C  = (size_t)64 * CW * 4;
    constexpr size_t SZ = SZ_AB > SZ_C ? SZ_AB : SZ_C;

    __shared__ __align__(16) char smraw[SZ];
    __half* As = (__half*)smraw;
    __half* Bs = As + 64 * AW;
    float*  Cs = (float*)smraw;

    int tid = threadIdx.x;
    int row0 = blockIdx.x * 64;

#pragma unroll
    for (int j = tid; j < 64 * (K / 4); j += 256) {
        int r = j / (K / 4), c4 = j % (K / 4);
        uint2 u = __ldg((const uint2*)g_x1h + (size_t)(row0 + r) * (K / 4) + c4);
        *(uint2*)&As[r * AW + c4 * 4] = u;
    }
#pragma unroll
    for (int j = tid; j < K * (N / 4); j += 256) {
        float4 w = __ldg((const float4*)W + j);
        int r = j / (N / 4), c4 = j % (N / 4);
        *(uint2*)&Bs[r * BW + c4 * 4] = pack_h4(w);
    }
    __syncthreads();

    int w = tid >> 5;
    int rt = w & 3;
    int ch = w >> 2;
    int col_base = ch * (N / 2);

    wmma::fragment<wmma::accumulator, 16, 16, 16, float> acc[CT];
#pragma unroll
    for (int t = 0; t < CT; ++t) wmma::fill_fragment(acc[t], 0.0f);
#pragma unroll
    for (int k0 = 0; k0 < K / 16; ++k0) {
        wmma::fragment<wmma::matrix_a, 16, 16, 16, __half, wmma::row_major> fa;
        wmma::load_matrix_sync(fa, As + rt * 16 * AW + k0 * 16, AW);
#pragma unroll
        for (int t = 0; t < CT; ++t) {
            wmma::fragment<wmma::matrix_b, 16, 16, 16, __half, wmma::row_major> fb;
            wmma::load_matrix_sync(fb, Bs + (k0 * 16) * BW + col_base + t * 16, BW);
            wmma::mma_sync(acc[t], fa, fb, acc[t]);
        }
    }
    __syncthreads();
#pragma unroll
    for (int t = 0; t < CT; ++t)
        wmma::store_matrix_sync(Cs + rt * 16 * CW + col_base + t * 16, acc[t], CW,
                                wmma::mem_row_major);
    __syncthreads();

#pragma unroll
    for (int j = tid; j < 64 * (N / 4); j += 256) {
        int r = j / (N / 4), c4 = j % (N / 4);
        float4 v = *(float4*)&Cs[r * CW + c4 * 4];
        float sc = g_dinv[row0 + r];
        v.x *= sc; v.y *= sc; v.z *= sc; v.w *= sc;
        g_hs2h[(size_t)(row0 + r) * 16 + c4] = pack_h4(v);
    }
}

extern "C" void kernel_launch(void* const* d_in, const int* in_sizes, int n_in,
                              void* d_out, int out_size) {
    const float* z   = (const float*)d_in[0];
    const int* ei    = (const int*)d_in[1];   // int32 OR int64 pairs (detected)
    const float* W1  = (const float*)d_in[2];
    const float* b1  = (const float*)d_in[3];
    const float* W2  = (const float*)d_in[4];
    const float* b2  = (const float*)d_in[5];
    float* out = (float*)d_out;

    void* cnt_ptr = nullptr;
    cudaGetSymbolAddress(&cnt_ptr, g_cnt);
    cudaMemsetAsync(cnt_ptr, 0, NN * sizeof(int));

    k_detect<<<1, 256>>>(ei);
    k_hist<<<(NE / 4 + 255) / 256, 256>>>(ei);
    k_scan1<<<SCAN_NB, SCAN_B>>>();
    k_prep<<<NN * 16 / 512, 256>>>((const float4*)z);
    k_permute<<<(NE / 4 + 255) / 256, 256>>>(ei);
    k_fused1<<<(NN + 63) / 64, 256>>>(W1, b1);
    k_gemm_wmma2<<<(NN + 63) / 64, 256>>>(W2);
    k_gather2<<<NN * 16 / 256, 256>>>((float4*)out, (const float4*)b2);
}